// round 12
// baseline (speedup 1.0000x reference)
#include <cuda_runtime.h>
#include <cuda_bf16.h>
#include <cstdint>

// DWTModelFullBand: reference = 2-level Haar DWT immediately inverted by its
// exact algebraic inverse (idwt2∘dwt2 = identity; stack/reshape is an identity
// permutation). x_rec == x up to ~6e-8 rel err. Irreducible work = 96MB copy.
//
// Converged model (R1-R10): dur_us = 192MB / ~5.43 TB/s mixed-r/w DRAM drain,
// pipelined across graph replays; kernel window is fully hidden. Traffic is
// irreducible (d_out poisoned each run; input read mandatory; both fp32).
// All levers tested — engine, MLP, full L2 hint matrix, phase batching —
// land within 35.29-35.58us. Write-through stores (R10) measured best.
//
// R11: combine the two best micro-choices: write-through stores (no deferred
// writeback drain; best dur_us) in the 256-bit v8.b32 encoding (fewest LSU
// issues, most bytes in flight per instruction; best kernel window).

#define VPT 2  // 32-byte chunks per thread

struct V8 { uint32_t r[8]; };

__device__ __forceinline__ V8 ld_stream_v8(const void* p) {
    V8 v;
    asm volatile(
        "ld.global.nc.L2::evict_first.v8.b32 {%0,%1,%2,%3,%4,%5,%6,%7}, [%8];"
        : "=r"(v.r[0]), "=r"(v.r[1]), "=r"(v.r[2]), "=r"(v.r[3]),
          "=r"(v.r[4]), "=r"(v.r[5]), "=r"(v.r[6]), "=r"(v.r[7])
        : "l"(p));
    return v;
}

__device__ __forceinline__ void st_wt_v8(void* p, const V8& v) {
    asm volatile(
        "st.global.wt.v8.b32 [%0], {%1,%2,%3,%4,%5,%6,%7,%8};"
        :: "l"(p),
           "r"(v.r[0]), "r"(v.r[1]), "r"(v.r[2]), "r"(v.r[3]),
           "r"(v.r[4]), "r"(v.r[5]), "r"(v.r[6]), "r"(v.r[7])
        : "memory");
}

__global__ void __launch_bounds__(256)
dwt_identity_copy_kernel(const char* __restrict__ in,
                         char* __restrict__ out,
                         long long half_bytes) {
    long long i = (long long)(blockIdx.x * blockDim.x + threadIdx.x) * 32;

    V8 v[VPT];
#pragma unroll
    for (int k = 0; k < VPT; k++)
        v[k] = ld_stream_v8(in + i + k * half_bytes);  // streaming 256-bit loads
#pragma unroll
    for (int k = 0; k < VPT; k++)
        st_wt_v8(out + i + k * half_bytes, v[k]);      // write-through 256-bit stores
}

extern "C" void kernel_launch(void* const* d_in, const int* in_sizes, int n_in,
                              void* d_out, int out_size) {
    const char* x = (const char*)d_in[0];
    char* out = (char*)d_out;

    // 100,663,296 bytes = 3,145,728 x 32B; 6144 blocks x 256 threads x 2.
    long long total_bytes = (long long)out_size * 4;
    long long half_bytes = total_bytes / VPT;
    int threads = 256;
    int blocks = (int)(half_bytes / 32 / threads);  // 6144

    dwt_identity_copy_kernel<<<blocks, threads>>>(x, out, half_bytes);
}

// round 14
// speedup vs baseline: 1.0082x; 1.0082x over previous
#include <cuda_runtime.h>
#include <cuda_bf16.h>

// DWTModelFullBand — FINAL KERNEL (converged, R12).
//
// The reference applies a 2-level Haar DWT and then exactly inverts it:
// idwt2 is the algebraic inverse of dwt2 (a=(ll-lh-hl+hh)/2 recovers a
// exactly, etc.), and the stack/reshape between the levels is an identity
// permutation. x_rec == x up to ~6e-8 rel err — 4 orders under the 1e-3
// gate. The irreducible work is a 96MB device-to-device fp32 copy.
//
// Converged performance model (12 rounds of experiments):
//   dur_us = 192MB irreducible DRAM traffic / ~5.43 TB/s achieved drain
//          ≈ 35.4us, pipelined across graph replays.
// Invariant to: copy engine vs SM path, per-warp MLP (1..8), the full L2
// eviction-hint matrix (evict_first/normal/last x input/output), CTA-level
// read/write phase batching, and 128- vs 256-bit access width — all land
// within a 35.29-35.58us noise band. Traffic is irreducible: the harness
// poisons d_out each run (96MB write mandatory) and the input must be read
// on every deterministic call (96MB read mandatory); L2 retains neither
// buffer across replays.
//
// Best-measured configuration (R10, 35.296us): one float4 per thread,
// __ldcs streaming load (evict-first, keeps L2 pressure minimal) and __stwt
// write-through store (no dirty lines -> no deferred writeback drain tail
// bleeding into the next replay), maximal 24576-block grid for the most
// even spread across the 192 LTS slices.

__global__ void __launch_bounds__(256)
dwt_identity_copy_kernel(const float4* __restrict__ in,
                         float4* __restrict__ out) {
    int i = blockIdx.x * blockDim.x + threadIdx.x;
    float4 v = __ldcs(in + i);   // streaming load
    __stwt(out + i, v);          // write-through store
}

extern "C" void kernel_launch(void* const* d_in, const int* in_sizes, int n_in,
                              void* d_out, int out_size) {
    const float4* x = (const float4*)d_in[0];
    float4* out = (float4*)d_out;

    // 25,165,824 floats = 6,291,456 float4 = 24576 blocks x 256 threads exactly.
    int n_vec4 = out_size / 4;
    int threads = 256;
    int blocks = n_vec4 / threads;

    dwt_identity_copy_kernel<<<blocks, threads>>>(x, out);
}